// round 4
// baseline (speedup 1.0000x reference)
#include <cuda_runtime.h>
#include <cstdint>
#include <cstddef>

#define N 8192
#define D 64

// ---- kernel 2 config ----
#define TI 128                 // i-columns (output rows) per CTA
#define JS 16                  // j-splits
#define JRANGE (N / JS)        // 512
#define CJ 128                 // j chunk per pipeline stage
#define NCHUNK (JRANGE / CJ)   // 4
#define BATCH 16               // A-scan rows per batch
#define NBATCH (CJ / BATCH)    // 8
#define CAP 32                 // max nnz per (i,128-chunk); data max ~18 for p=.05
#define K2T 128                // 4 warps

// scratch (static device arrays: allocation-free per harness rules)
__device__ float g_y[N * D];            // y = x@W_nobj + b_nobj   (2 MB)
__device__ float g_part[JS][N * D];     // j-split partials        (33.6 MB)

// ---------------------------------------------------------------------------
// Kernel 1: out = x@(W_obj+W_skip) + r@W_rel + biases ;  g_y = x@W_nobj+b_nobj
// ---------------------------------------------------------------------------
__global__ __launch_bounds__(256) void k1_proj(
    const float* __restrict__ x, const float* __restrict__ r,
    const float* __restrict__ W_obj, const float* __restrict__ b_obj,
    const float* __restrict__ W_nobj, const float* __restrict__ b_nobj,
    const float* __restrict__ W_rel, const float* __restrict__ b_rel,
    const float* __restrict__ W_skip, const float* __restrict__ b_skip,
    float* __restrict__ out)
{
    __shared__ float Wc[D * D];   // W_obj + W_skip
    __shared__ float Wn[D * D];   // W_nobj
    __shared__ float Wr[D * D];   // W_rel

    const int t = threadIdx.x;
    for (int e = t; e < D * D; e += 256) {
        Wc[e] = W_obj[e] + W_skip[e];
        Wn[e] = W_nobj[e];
        Wr[e] = W_rel[e];
    }
    __syncthreads();

    const int row = blockIdx.x * 32 + (t >> 3);
    const int d0 = (t & 7) * 8;

    float ab[8], ay[8];
#pragma unroll
    for (int q = 0; q < 8; q++) { ab[q] = 0.f; ay[q] = 0.f; }

    const float4* xp = (const float4*)(x + row * D);
    const float4* rp = (const float4*)(r + row * D);

#pragma unroll
    for (int k4 = 0; k4 < D / 4; k4++) {
        const float4 xq = xp[k4];
        const float4 rq = rp[k4];
        const float xv[4] = {xq.x, xq.y, xq.z, xq.w};
        const float rv[4] = {rq.x, rq.y, rq.z, rq.w};
#pragma unroll
        for (int u = 0; u < 4; u++) {
            const int k = k4 * 4 + u;
            const float4 c0 = *(const float4*)&Wc[k * D + d0];
            const float4 c1 = *(const float4*)&Wc[k * D + d0 + 4];
            const float4 n0 = *(const float4*)&Wn[k * D + d0];
            const float4 n1 = *(const float4*)&Wn[k * D + d0 + 4];
            const float4 q0 = *(const float4*)&Wr[k * D + d0];
            const float4 q1 = *(const float4*)&Wr[k * D + d0 + 4];
            const float cc[8] = {c0.x,c0.y,c0.z,c0.w,c1.x,c1.y,c1.z,c1.w};
            const float nn[8] = {n0.x,n0.y,n0.z,n0.w,n1.x,n1.y,n1.z,n1.w};
            const float qq[8] = {q0.x,q0.y,q0.z,q0.w,q1.x,q1.y,q1.z,q1.w};
#pragma unroll
            for (int q = 0; q < 8; q++) {
                ab[q] += xv[u] * cc[q] + rv[u] * qq[q];
                ay[q] += xv[u] * nn[q];
            }
        }
    }

    // vectorized epilogue (float4 stores)
    float4 o0, o1, y0, y1;
    o0.x = ab[0]+b_obj[d0+0]+b_skip[d0+0]+b_rel[d0+0];
    o0.y = ab[1]+b_obj[d0+1]+b_skip[d0+1]+b_rel[d0+1];
    o0.z = ab[2]+b_obj[d0+2]+b_skip[d0+2]+b_rel[d0+2];
    o0.w = ab[3]+b_obj[d0+3]+b_skip[d0+3]+b_rel[d0+3];
    o1.x = ab[4]+b_obj[d0+4]+b_skip[d0+4]+b_rel[d0+4];
    o1.y = ab[5]+b_obj[d0+5]+b_skip[d0+5]+b_rel[d0+5];
    o1.z = ab[6]+b_obj[d0+6]+b_skip[d0+6]+b_rel[d0+6];
    o1.w = ab[7]+b_obj[d0+7]+b_skip[d0+7]+b_rel[d0+7];
    y0.x = ay[0]+b_nobj[d0+0]; y0.y = ay[1]+b_nobj[d0+1];
    y0.z = ay[2]+b_nobj[d0+2]; y0.w = ay[3]+b_nobj[d0+3];
    y1.x = ay[4]+b_nobj[d0+4]; y1.y = ay[5]+b_nobj[d0+5];
    y1.z = ay[6]+b_nobj[d0+6]; y1.w = ay[7]+b_nobj[d0+7];
    float4* op = (float4*)(out + row * D + d0);
    float4* yp = (float4*)(g_y + row * D + d0);
    op[0] = o0; op[1] = o1;
    yp[0] = y0; yp[1] = y1;
}

// ---------------------------------------------------------------------------
// Kernel 2: g_part[jy][i][:] = sum_{j in split jy} A[j][i] * y[j][:]
// Uniform warps, software-pipelined: per 16-row scan batch -> issue 16 LDGs,
// gather a 4-row slot of the PREVIOUS chunk while they fly, then compact.
// uchar4-batched gather gives MLP=4 on the y LDS.64s. One sync per chunk.
// ---------------------------------------------------------------------------
__device__ __forceinline__ void gather4(
    int base_row, int w, int lane,
    const float* ybuf, const unsigned char* lbuf, const int* cbuf,
    float* accx, float* accy)
{
    const float2* y2 = (const float2*)ybuf;
#pragma unroll
    for (int rr = 0; rr < 4; rr++) {
        const int rloc = base_row + rr;              // 0..31 (compile-time w/ unroll)
        const int iloc = (w << 5) | rloc;
        const int cn = cbuf[iloc];                   // warp-uniform
        const uchar4* lp4 = (const uchar4*)(lbuf + iloc * CAP);
        float ax = 0.f, ay = 0.f;
        int e = 0;
        for (; e + 4 <= cn; e += 4) {
            const uchar4 j4 = lp4[e >> 2];           // LDS broadcast
            const float2 v0 = y2[j4.x * 32 + lane];  // 4 independent LDS.64
            const float2 v1 = y2[j4.y * 32 + lane];
            const float2 v2 = y2[j4.z * 32 + lane];
            const float2 v3 = y2[j4.w * 32 + lane];
            ax += v0.x; ay += v0.y;
            ax += v1.x; ay += v1.y;
            ax += v2.x; ay += v2.y;
            ax += v3.x; ay += v3.y;
        }
        const unsigned char* lp = lbuf + iloc * CAP;
        for (; e < cn; e++) {
            const float2 v = y2[lp[e] * 32 + lane];
            ax += v.x; ay += v.y;
        }
        accx[rloc] += ax; accy[rloc] += ay;
    }
}

__global__ __launch_bounds__(K2T, 3) void k2_spmm(const float* __restrict__ A)
{
    extern __shared__ float sm[];
    float* y_s[2];
    y_s[0] = sm;                                          // [CJ][D] 32 KB
    y_s[1] = sm + CJ * D;                                 // [CJ][D] 32 KB
    unsigned char* lst[2];
    lst[0] = (unsigned char*)(sm + 2 * CJ * D);           // [TI][CAP] 4 KB
    lst[1] = lst[0] + TI * CAP;                           // [TI][CAP] 4 KB
    int* cnt[2];
    cnt[0] = (int*)(lst[1] + TI * CAP);                   // [TI]
    cnt[1] = cnt[0] + TI;                                 // [TI]

    const int t = threadIdx.x;
    const int w = t >> 5, lane = t & 31;
    const int i_base = blockIdx.x * TI;
    const int jy = blockIdx.y;
    const int j_base = jy * JRANGE;

    float accx[32], accy[32];
#pragma unroll
    for (int il = 0; il < 32; il++) { accx[il] = 0.f; accy[il] = 0.f; }

    // prologue: stage y chunk 0
    {
        const float4* ys = (const float4*)(g_y + (size_t)j_base * D);
        float4* yd = (float4*)y_s[0];
#pragma unroll
        for (int e = 0; e < (CJ * D / 4) / K2T; e++)      // 16
            yd[e * K2T + t] = ys[e * K2T + t];
    }
    __syncthreads();

    for (int c = 0; c < NCHUNK; c++) {
        const int cb = c & 1, pb = (c - 1) & 1;
        const float* Ac = A + (size_t)(j_base + c * CJ) * N + (i_base + t);
        unsigned char* lw = lst[cb] + t * CAP;
        const float* ygather = y_s[pb];
        int cnt_r = 0;

#pragma unroll
        for (int b = 0; b < NBATCH; b++) {                // 8 batches, unrolled
            float av[BATCH];
#pragma unroll
            for (int u = 0; u < BATCH; u++)               // issue 16 LDGs
                av[u] = __ldcs(Ac + (size_t)(b * BATCH + u) * N);

            if (c > 0)                                    // hide LDG latency
                gather4(b * 4, w, lane, ygather, lst[pb], cnt[pb], accx, accy);

#pragma unroll
            for (int u = 0; u < BATCH; u++) {             // compact
                if (av[u] != 0.0f) {
                    if (cnt_r < CAP) lw[cnt_r] = (unsigned char)(b * BATCH + u);
                    cnt_r++;
                }
            }
        }
        cnt[cb][t] = (cnt_r < CAP) ? cnt_r : CAP;

        if (c + 1 < NCHUNK) {                             // stage y chunk c+1
            const float4* ys = (const float4*)(g_y + (size_t)(j_base + (c + 1) * CJ) * D);
            float4* yd = (float4*)y_s[(c + 1) & 1];
#pragma unroll
            for (int e = 0; e < (CJ * D / 4) / K2T; e++)
                yd[e * K2T + t] = ys[e * K2T + t];
        }
        __syncthreads();
    }

    // epilogue: gather last chunk
    {
        const int pb = (NCHUNK - 1) & 1;
#pragma unroll
        for (int b = 0; b < NBATCH; b++)
            gather4(b * 4, w, lane, y_s[pb], lst[pb], cnt[pb], accx, accy);
    }

    // write partial tile straight from registers
#pragma unroll
    for (int il = 0; il < 32; il++) {
        const int i = i_base + (w << 5) + il;
        ((float2*)&g_part[jy][(size_t)i * D])[lane] = make_float2(accx[il], accy[il]);
    }
}

// ---------------------------------------------------------------------------
// Kernel 3: out += sum over the JS partials (fixed order -> deterministic)
// ---------------------------------------------------------------------------
__global__ __launch_bounds__(256) void k3_reduce(float* __restrict__ out)
{
    const int g = blockIdx.x * blockDim.x + threadIdx.x;   // over N*D/4 float4s
    float4 v = ((const float4*)out)[g];
#pragma unroll
    for (int s = 0; s < JS; s++) {
        const float4 p = ((const float4*)(&g_part[s][0]))[g];
        v.x += p.x; v.y += p.y; v.z += p.z; v.w += p.w;
    }
    ((float4*)out)[g] = v;
}

// ---------------------------------------------------------------------------
extern "C" void kernel_launch(void* const* d_in, const int* in_sizes, int n_in,
                              void* d_out, int out_size)
{
    const float* x      = (const float*)d_in[0];
    const float* r      = (const float*)d_in[1];
    const float* A      = (const float*)d_in[2];
    const float* W_obj  = (const float*)d_in[3];
    const float* b_obj  = (const float*)d_in[4];
    const float* W_nobj = (const float*)d_in[5];
    const float* b_nobj = (const float*)d_in[6];
    const float* W_rel  = (const float*)d_in[7];
    const float* b_rel  = (const float*)d_in[8];
    const float* W_skip = (const float*)d_in[9];
    const float* b_skip = (const float*)d_in[10];
    // d_in[11]/d_in[12] (Wa_w, Wa_b) provably cancel: softmax rows sum to 1,
    // so the attention term is the identity on `aggregated`.
    float* out = (float*)d_out;

    const size_t sm2 = 2 * ((size_t)CJ * D * 4)      // y double buffer  64 KB
                     + 2 * ((size_t)TI * CAP)        // list buffers      8 KB
                     + 2 * ((size_t)TI * 4);         // cnt buffers       1 KB
    cudaFuncSetAttribute(k2_spmm, cudaFuncAttributeMaxDynamicSharedMemorySize, (int)sm2);

    k1_proj<<<N / 32, 256>>>(x, r, W_obj, b_obj, W_nobj, b_nobj,
                             W_rel, b_rel, W_skip, b_skip, out);
    k2_spmm<<<dim3(N / TI, JS), K2T, sm2>>>(A);
    k3_reduce<<<(N * D / 4) / 256, 256>>>(out);
}

// round 5
// speedup vs baseline: 1.0721x; 1.0721x over previous
#include <cuda_runtime.h>
#include <cstdint>
#include <cstddef>

#define N 8192
#define D 64

// ---- kernel 2 config ----
#define TI 64                  // i-columns (output rows) per CTA == threads
#define JS 16                  // j-splits
#define JRANGE (N / JS)        // 512
#define CJ 128                 // j chunk per stage
#define NCHUNK (JRANGE / CJ)   // 4
#define BATCH 16               // A-scan rows per batch
#define NBATCH (CJ / BATCH)    // 8
#define CAP 32                 // max nnz per (i,128-chunk); Bin(128,.05) P(>=32)~4e-13
#define K2T 64                 // 2 warps

// scratch (static device arrays: allocation-free per harness rules)
__device__ float g_y[N * D];            // y = x@W_nobj + b_nobj   (2 MB)
__device__ float g_part[JS][N * D];     // j-split partials        (33.6 MB)

// ---------------------------------------------------------------------------
__device__ __forceinline__ void cp_async16(uint32_t saddr, const void* gptr) {
    asm volatile("cp.async.cg.shared.global [%0], [%1], 16;" :: "r"(saddr), "l"(gptr));
}
__device__ __forceinline__ void cp_commit() { asm volatile("cp.async.commit_group;"); }
__device__ __forceinline__ void cp_wait0()  { asm volatile("cp.async.wait_group 0;"); }

// ---------------------------------------------------------------------------
// Kernel 1: out = x@(W_obj+W_skip) + r@W_rel + biases ;  g_y = x@W_nobj+b_nobj
// 128 threads (16 rows), grid 512 for wave balance.
// ---------------------------------------------------------------------------
__global__ __launch_bounds__(128) void k1_proj(
    const float* __restrict__ x, const float* __restrict__ r,
    const float* __restrict__ W_obj, const float* __restrict__ b_obj,
    const float* __restrict__ W_nobj, const float* __restrict__ b_nobj,
    const float* __restrict__ W_rel, const float* __restrict__ b_rel,
    const float* __restrict__ W_skip, const float* __restrict__ b_skip,
    float* __restrict__ out)
{
    __shared__ float Wc[D * D];   // W_obj + W_skip
    __shared__ float Wn[D * D];   // W_nobj
    __shared__ float Wr[D * D];   // W_rel

    const int t = threadIdx.x;
    for (int e = t; e < D * D; e += 128) {
        Wc[e] = W_obj[e] + W_skip[e];
        Wn[e] = W_nobj[e];
        Wr[e] = W_rel[e];
    }
    __syncthreads();

    const int row = blockIdx.x * 16 + (t >> 3);
    const int d0 = (t & 7) * 8;

    float ab[8], ay[8];
#pragma unroll
    for (int q = 0; q < 8; q++) { ab[q] = 0.f; ay[q] = 0.f; }

    const float4* xp = (const float4*)(x + row * D);
    const float4* rp = (const float4*)(r + row * D);

#pragma unroll
    for (int k4 = 0; k4 < D / 4; k4++) {
        const float4 xq = xp[k4];
        const float4 rq = rp[k4];
        const float xv[4] = {xq.x, xq.y, xq.z, xq.w};
        const float rv[4] = {rq.x, rq.y, rq.z, rq.w};
#pragma unroll
        for (int u = 0; u < 4; u++) {
            const int k = k4 * 4 + u;
            const float4 c0 = *(const float4*)&Wc[k * D + d0];
            const float4 c1 = *(const float4*)&Wc[k * D + d0 + 4];
            const float4 n0 = *(const float4*)&Wn[k * D + d0];
            const float4 n1 = *(const float4*)&Wn[k * D + d0 + 4];
            const float4 q0 = *(const float4*)&Wr[k * D + d0];
            const float4 q1 = *(const float4*)&Wr[k * D + d0 + 4];
            const float cc[8] = {c0.x,c0.y,c0.z,c0.w,c1.x,c1.y,c1.z,c1.w};
            const float nn[8] = {n0.x,n0.y,n0.z,n0.w,n1.x,n1.y,n1.z,n1.w};
            const float qq[8] = {q0.x,q0.y,q0.z,q0.w,q1.x,q1.y,q1.z,q1.w};
#pragma unroll
            for (int q = 0; q < 8; q++) {
                ab[q] += xv[u] * cc[q] + rv[u] * qq[q];
                ay[q] += xv[u] * nn[q];
            }
        }
    }

    float4 o0, o1, y0, y1;
    o0.x = ab[0]+b_obj[d0+0]+b_skip[d0+0]+b_rel[d0+0];
    o0.y = ab[1]+b_obj[d0+1]+b_skip[d0+1]+b_rel[d0+1];
    o0.z = ab[2]+b_obj[d0+2]+b_skip[d0+2]+b_rel[d0+2];
    o0.w = ab[3]+b_obj[d0+3]+b_skip[d0+3]+b_rel[d0+3];
    o1.x = ab[4]+b_obj[d0+4]+b_skip[d0+4]+b_rel[d0+4];
    o1.y = ab[5]+b_obj[d0+5]+b_skip[d0+5]+b_rel[d0+5];
    o1.z = ab[6]+b_obj[d0+6]+b_skip[d0+6]+b_rel[d0+6];
    o1.w = ab[7]+b_obj[d0+7]+b_skip[d0+7]+b_rel[d0+7];
    y0.x = ay[0]+b_nobj[d0+0]; y0.y = ay[1]+b_nobj[d0+1];
    y0.z = ay[2]+b_nobj[d0+2]; y0.w = ay[3]+b_nobj[d0+3];
    y1.x = ay[4]+b_nobj[d0+4]; y1.y = ay[5]+b_nobj[d0+5];
    y1.z = ay[6]+b_nobj[d0+6]; y1.w = ay[7]+b_nobj[d0+7];
    float4* op = (float4*)(out + row * D + d0);
    float4* yp = (float4*)(g_y + row * D + d0);
    op[0] = o0; op[1] = o1;
    yp[0] = y0; yp[1] = y1;
}

// ---------------------------------------------------------------------------
// Kernel 2: g_part[jy][i][:] = sum_{j in split jy} A[j][i] * y[j][:]
// 64-thread CTAs (6/SM): cross-CTA overlap hides per-CTA phase serialization.
// Per chunk: [cp.async y issued previous phase] -> pipelined A scan (double-
// buffered 16-deep LDG batches) -> barrier -> uchar4 MLP-4 gather -> barrier
// -> issue cp.async for next y chunk.
// Deterministic: j ascending in chunk, chunks ascending, k3 fixed order.
// ---------------------------------------------------------------------------
__global__ __launch_bounds__(K2T, 6) void k2_spmm(const float* __restrict__ A)
{
    extern __shared__ float sm[];
    float* y_s = sm;                                      // [CJ][D]  32 KB
    unsigned char* lst = (unsigned char*)(y_s + CJ * D);  // [TI][CAP] 2 KB
    int* cnt_s = (int*)(lst + TI * CAP);                  // [TI]     256 B

    const int t = threadIdx.x;
    const int w = t >> 5, lane = t & 31;
    const int i_base = blockIdx.x * TI;
    const int jy = blockIdx.y;
    const int j_base = jy * JRANGE;

    float accx[32], accy[32];
#pragma unroll
    for (int il = 0; il < 32; il++) { accx[il] = 0.f; accy[il] = 0.f; }

    // prologue: issue async stage of y chunk 0 (flies during first scan)
    {
        const float4* ys = (const float4*)(g_y + (size_t)j_base * D);
        uint32_t yd = (uint32_t)__cvta_generic_to_shared(y_s);
#pragma unroll
        for (int e = 0; e < (CJ * D / 4) / K2T; e++)      // 32 per thread
            cp_async16(yd + (e * K2T + t) * 16, ys + e * K2T + t);
        cp_commit();
    }

    for (int c = 0; c < NCHUNK; c++) {
        // ---------- scan A chunk c (LDG double-buffered batches) ----------
        {
            const float* Ac = A + (size_t)(j_base + c * CJ) * N + (i_base + t);
            unsigned char* lw = lst + t * CAP;
            int cnt = 0;
            float av0[BATCH], av1[BATCH];
#pragma unroll
            for (int u = 0; u < BATCH; u++)
                av0[u] = __ldcs(Ac + (size_t)u * N);
#pragma unroll
            for (int b = 0; b < NBATCH; b += 2) {
                // issue batch b+1 while compacting b
#pragma unroll
                for (int u = 0; u < BATCH; u++)
                    av1[u] = __ldcs(Ac + (size_t)((b + 1) * BATCH + u) * N);
#pragma unroll
                for (int u = 0; u < BATCH; u++) {
                    if (av0[u] != 0.0f) {
                        if (cnt < CAP) lw[cnt] = (unsigned char)(b * BATCH + u);
                        cnt++;
                    }
                }
                // issue batch b+2 while compacting b+1
                if (b + 2 < NBATCH) {
#pragma unroll
                    for (int u = 0; u < BATCH; u++)
                        av0[u] = __ldcs(Ac + (size_t)((b + 2) * BATCH + u) * N);
                }
#pragma unroll
                for (int u = 0; u < BATCH; u++) {
                    if (av1[u] != 0.0f) {
                        if (cnt < CAP) lw[cnt] = (unsigned char)((b + 1) * BATCH + u);
                        cnt++;
                    }
                }
            }
            cnt_s[t] = (cnt < CAP) ? cnt : CAP;
        }

        cp_wait0();          // y chunk c staged
        __syncthreads();     // y + lists visible CTA-wide

        // ---------- gather chunk c: warp w -> rows w*32..+31, uchar4 MLP-4 ----------
        {
            const float2* y2 = (const float2*)y_s;
#pragma unroll
            for (int il = 0; il < 32; il++) {
                const int iloc = (w << 5) | il;
                const int cn = cnt_s[iloc];                   // warp-uniform
                const unsigned char* lp = lst + iloc * CAP;
                float ax = 0.f, ay = 0.f;
                int e = 0;
                for (; e + 4 <= cn; e += 4) {
                    const uchar4 j4 = *(const uchar4*)(lp + e);   // LDS broadcast
                    const float2 v0 = y2[j4.x * 32 + lane];       // 4 indep LDS.64
                    const float2 v1 = y2[j4.y * 32 + lane];
                    const float2 v2 = y2[j4.z * 32 + lane];
                    const float2 v3 = y2[j4.w * 32 + lane];
                    ax += v0.x; ay += v0.y;
                    ax += v1.x; ay += v1.y;
                    ax += v2.x; ay += v2.y;
                    ax += v3.x; ay += v3.y;
                }
                for (; e < cn; e++) {
                    const float2 v = y2[lp[e] * 32 + lane];
                    ax += v.x; ay += v.y;
                }
                accx[il] += ax; accy[il] += ay;
            }
        }
        __syncthreads();     // y buffer free for restage

        // ---------- issue async stage of y chunk c+1 (overlaps next scan) ----------
        if (c + 1 < NCHUNK) {
            const float4* ys = (const float4*)(g_y + (size_t)(j_base + (c + 1) * CJ) * D);
            uint32_t yd = (uint32_t)__cvta_generic_to_shared(y_s);
#pragma unroll
            for (int e = 0; e < (CJ * D / 4) / K2T; e++)
                cp_async16(yd + (e * K2T + t) * 16, ys + e * K2T + t);
            cp_commit();
        }
    }

    // write partial tile straight from registers
#pragma unroll
    for (int il = 0; il < 32; il++) {
        const int i = i_base + (w << 5) + il;
        ((float2*)&g_part[jy][(size_t)i * D])[lane] = make_float2(accx[il], accy[il]);
    }
}

// ---------------------------------------------------------------------------
// Kernel 3: out += sum over the JS partials (fixed order -> deterministic)
// ---------------------------------------------------------------------------
__global__ __launch_bounds__(256) void k3_reduce(float* __restrict__ out)
{
    const int g = blockIdx.x * blockDim.x + threadIdx.x;   // over N*D/4 float4s
    float4 v = ((const float4*)out)[g];
#pragma unroll
    for (int s = 0; s < JS; s++) {
        const float4 p = ((const float4*)(&g_part[s][0]))[g];
        v.x += p.x; v.y += p.y; v.z += p.z; v.w += p.w;
    }
    ((float4*)out)[g] = v;
}

// ---------------------------------------------------------------------------
extern "C" void kernel_launch(void* const* d_in, const int* in_sizes, int n_in,
                              void* d_out, int out_size)
{
    const float* x      = (const float*)d_in[0];
    const float* r      = (const float*)d_in[1];
    const float* A      = (const float*)d_in[2];
    const float* W_obj  = (const float*)d_in[3];
    const float* b_obj  = (const float*)d_in[4];
    const float* W_nobj = (const float*)d_in[5];
    const float* b_nobj = (const float*)d_in[6];
    const float* W_rel  = (const float*)d_in[7];
    const float* b_rel  = (const float*)d_in[8];
    const float* W_skip = (const float*)d_in[9];
    const float* b_skip = (const float*)d_in[10];
    // d_in[11]/d_in[12] (Wa_w, Wa_b) provably cancel: softmax rows sum to 1,
    // so the attention term is the identity on `aggregated`.
    float* out = (float*)d_out;

    const size_t sm2 = (size_t)CJ * D * 4        // y buffer   32 KB
                     + (size_t)TI * CAP          // lists       2 KB
                     + (size_t)TI * 4;           // counts    256 B
    cudaFuncSetAttribute(k2_spmm, cudaFuncAttributeMaxDynamicSharedMemorySize, (int)sm2);

    k1_proj<<<N / 16, 128>>>(x, r, W_obj, b_obj, W_nobj, b_nobj,
                             W_rel, b_rel, W_skip, b_skip, out);
    k2_spmm<<<dim3(N / TI, JS), K2T, sm2>>>(A);
    k3_reduce<<<(N * D / 4) / 256, 256>>>(out);
}

// round 6
// speedup vs baseline: 1.6759x; 1.5633x over previous
#include <cuda_runtime.h>
#include <cstdint>
#include <cstddef>

#define N 8192
#define D 64

// ---- k2 config ----
#define TI 128                 // A-columns per CTA (both k2a and k2b)
#define JS 16                  // j-splits
#define JRANGE (N / JS)        // 512
#define CJ 128                 // j's per mask chunk / y stage
#define NCHUNK (JRANGE / CJ)   // 4

// scratch (static device arrays: allocation-free per harness rules)
__device__ float g_y[N * D];                      // y = x@W_nobj + b_nobj (2 MB)
__device__ float g_part[JS][N * D];               // j-split partials (33.6 MB)
__device__ uint4 g_mask[JS * NCHUNK * N];         // bitmasks (8.4 MB)

// ---------------------------------------------------------------------------
// Kernel 1: out = x@(W_obj+W_skip) + r@W_rel + biases ;  g_y = x@W_nobj+b_nobj
// ---------------------------------------------------------------------------
__global__ __launch_bounds__(128) void k1_proj(
    const float* __restrict__ x, const float* __restrict__ r,
    const float* __restrict__ W_obj, const float* __restrict__ b_obj,
    const float* __restrict__ W_nobj, const float* __restrict__ b_nobj,
    const float* __restrict__ W_rel, const float* __restrict__ b_rel,
    const float* __restrict__ W_skip, const float* __restrict__ b_skip,
    float* __restrict__ out)
{
    __shared__ float Wc[D * D];
    __shared__ float Wn[D * D];
    __shared__ float Wr[D * D];

    const int t = threadIdx.x;
    for (int e = t; e < D * D; e += 128) {
        Wc[e] = W_obj[e] + W_skip[e];
        Wn[e] = W_nobj[e];
        Wr[e] = W_rel[e];
    }
    __syncthreads();

    const int row = blockIdx.x * 16 + (t >> 3);
    const int d0 = (t & 7) * 8;

    float ab[8], ay[8];
#pragma unroll
    for (int q = 0; q < 8; q++) { ab[q] = 0.f; ay[q] = 0.f; }

    const float4* xp = (const float4*)(x + row * D);
    const float4* rp = (const float4*)(r + row * D);

#pragma unroll
    for (int k4 = 0; k4 < D / 4; k4++) {
        const float4 xq = xp[k4];
        const float4 rq = rp[k4];
        const float xv[4] = {xq.x, xq.y, xq.z, xq.w};
        const float rv[4] = {rq.x, rq.y, rq.z, rq.w};
#pragma unroll
        for (int u = 0; u < 4; u++) {
            const int k = k4 * 4 + u;
            const float4 c0 = *(const float4*)&Wc[k * D + d0];
            const float4 c1 = *(const float4*)&Wc[k * D + d0 + 4];
            const float4 n0 = *(const float4*)&Wn[k * D + d0];
            const float4 n1 = *(const float4*)&Wn[k * D + d0 + 4];
            const float4 q0 = *(const float4*)&Wr[k * D + d0];
            const float4 q1 = *(const float4*)&Wr[k * D + d0 + 4];
            const float cc[8] = {c0.x,c0.y,c0.z,c0.w,c1.x,c1.y,c1.z,c1.w};
            const float nn[8] = {n0.x,n0.y,n0.z,n0.w,n1.x,n1.y,n1.z,n1.w};
            const float qq[8] = {q0.x,q0.y,q0.z,q0.w,q1.x,q1.y,q1.z,q1.w};
#pragma unroll
            for (int q = 0; q < 8; q++) {
                ab[q] += xv[u] * cc[q] + rv[u] * qq[q];
                ay[q] += xv[u] * nn[q];
            }
        }
    }

    float4 o0, o1, y0, y1;
    o0.x = ab[0]+b_obj[d0+0]+b_skip[d0+0]+b_rel[d0+0];
    o0.y = ab[1]+b_obj[d0+1]+b_skip[d0+1]+b_rel[d0+1];
    o0.z = ab[2]+b_obj[d0+2]+b_skip[d0+2]+b_rel[d0+2];
    o0.w = ab[3]+b_obj[d0+3]+b_skip[d0+3]+b_rel[d0+3];
    o1.x = ab[4]+b_obj[d0+4]+b_skip[d0+4]+b_rel[d0+4];
    o1.y = ab[5]+b_obj[d0+5]+b_skip[d0+5]+b_rel[d0+5];
    o1.z = ab[6]+b_obj[d0+6]+b_skip[d0+6]+b_rel[d0+6];
    o1.w = ab[7]+b_obj[d0+7]+b_skip[d0+7]+b_rel[d0+7];
    y0.x = ay[0]+b_nobj[d0+0]; y0.y = ay[1]+b_nobj[d0+1];
    y0.z = ay[2]+b_nobj[d0+2]; y0.w = ay[3]+b_nobj[d0+3];
    y1.x = ay[4]+b_nobj[d0+4]; y1.y = ay[5]+b_nobj[d0+5];
    y1.z = ay[6]+b_nobj[d0+6]; y1.w = ay[7]+b_nobj[d0+7];
    float4* op = (float4*)(out + row * D + d0);
    float4* yp = (float4*)(g_y + row * D + d0);
    op[0] = o0; op[1] = o1;
    yp[0] = y0; yp[1] = y1;
}

// ---------------------------------------------------------------------------
// Kernel 2a: pure A stream -> bitmasks. Thread t owns column i_base+t.
// Per 128-j chunk: 4 double-buffered 32-deep LDG batches -> 4 mask words ->
// one coalesced STG.128. No smem, no syncs: nothing blocks the stream.
// ---------------------------------------------------------------------------
__global__ __launch_bounds__(128, 6) void k2a_scan(const float* __restrict__ A)
{
    const int t = threadIdx.x;
    const int i = blockIdx.x * TI + t;
    const int jy = blockIdx.y;
    const size_t j_base = (size_t)jy * JRANGE;

    float av0[32], av1[32];
    const float* Ac0 = A + j_base * N + i;

    // prefetch first batch
#pragma unroll
    for (int u = 0; u < 32; u++)
        av0[u] = __ldcs(Ac0 + (size_t)u * N);

    for (int c = 0; c < NCHUNK; c++) {
        const float* Ac = A + (j_base + c * CJ) * N + i;
        unsigned mw[4];
#pragma unroll
        for (int b = 0; b < 4; b++) {
            // issue next batch (possibly next chunk's batch 0) while packing
            const bool last = (c == NCHUNK - 1) && (b == 3);
            if (!last) {
                const float* Anext = (b < 3) ? (Ac + (size_t)(b + 1) * 32 * N)
                                             : (A + (j_base + (c + 1) * CJ) * N + i);
                if (b & 1) {
#pragma unroll
                    for (int u = 0; u < 32; u++) av0[u] = __ldcs(Anext + (size_t)u * N);
                } else {
#pragma unroll
                    for (int u = 0; u < 32; u++) av1[u] = __ldcs(Anext + (size_t)u * N);
                }
            }
            const float* cur = (b & 1) ? av1 : av0;
            unsigned m = 0;
#pragma unroll
            for (int u = 0; u < 32; u++)
                if (cur[u] != 0.0f) m |= (1u << u);
            mw[b] = m;
        }
        g_mask[((size_t)jy * NCHUNK + c) * N + i] = make_uint4(mw[0], mw[1], mw[2], mw[3]);
    }
}

// ---------------------------------------------------------------------------
// Kernel 2b: gather. Per CTA: 128 rows (i) x one j-split. Per chunk: stage y
// (32 KB smem), warp w walks rows w*32..+31 via broadcast uint4 mask + ffs,
// lane owns d-pair; conflict-free LDS.64; register accumulators.
// ---------------------------------------------------------------------------
__global__ __launch_bounds__(128, 4) void k2b_gather()
{
    __shared__ float y_s[CJ * D];   // 32 KB

    const int t = threadIdx.x;
    const int w = t >> 5, lane = t & 31;
    const int i_base = blockIdx.x * TI;
    const int jy = blockIdx.y;
    const size_t j_base = (size_t)jy * JRANGE;

    float accx[32], accy[32];
#pragma unroll
    for (int il = 0; il < 32; il++) { accx[il] = 0.f; accy[il] = 0.f; }

    for (int c = 0; c < NCHUNK; c++) {
        // ---- stage y chunk (L2-resident) ----
        {
            const float4* ys = (const float4*)(g_y + (j_base + c * CJ) * D);
            float4* yd = (float4*)y_s;
#pragma unroll
            for (int e = 0; e < (CJ * D / 4) / 128; e++)   // 16
                yd[e * 128 + t] = ys[e * 128 + t];
        }
        __syncthreads();

        const uint4* mrow = g_mask + ((size_t)jy * NCHUNK + c) * N + i_base;
        const float2* y2 = (const float2*)y_s;

#pragma unroll 4
        for (int il = 0; il < 32; il++) {
            const int iloc = (w << 5) | il;
            const uint4 m = __ldg(mrow + iloc);       // uniform across warp
            float ax = 0.f, ay = 0.f;
            const unsigned mwords[4] = {m.x, m.y, m.z, m.w};
#pragma unroll
            for (int k4 = 0; k4 < 4; k4++) {
                unsigned mm = mwords[k4];
                while (mm) {
                    const int b = __ffs(mm) - 1;
                    mm &= mm - 1;
                    const float2 v = y2[(k4 * 32 + b) * 32 + lane];
                    ax += v.x; ay += v.y;
                }
            }
            accx[iloc & 31] += ax;   // iloc&31 == il
            accy[iloc & 31] += ay;
        }
        __syncthreads();   // y_s free for restage
    }

    // write partial tile straight from registers
#pragma unroll
    for (int il = 0; il < 32; il++) {
        const int i = i_base + (w << 5) + il;
        ((float2*)&g_part[jy][(size_t)i * D])[lane] = make_float2(accx[il], accy[il]);
    }
}

// ---------------------------------------------------------------------------
// Kernel 3: out += sum over the JS partials (fixed order -> deterministic)
// ---------------------------------------------------------------------------
__global__ __launch_bounds__(256) void k3_reduce(float* __restrict__ out)
{
    const int g = blockIdx.x * blockDim.x + threadIdx.x;
    float4 v = ((const float4*)out)[g];
#pragma unroll
    for (int s = 0; s < JS; s++) {
        const float4 p = ((const float4*)(&g_part[s][0]))[g];
        v.x += p.x; v.y += p.y; v.z += p.z; v.w += p.w;
    }
    ((float4*)out)[g] = v;
}

// ---------------------------------------------------------------------------
extern "C" void kernel_launch(void* const* d_in, const int* in_sizes, int n_in,
                              void* d_out, int out_size)
{
    const float* x      = (const float*)d_in[0];
    const float* r      = (const float*)d_in[1];
    const float* A      = (const float*)d_in[2];
    const float* W_obj  = (const float*)d_in[3];
    const float* b_obj  = (const float*)d_in[4];
    const float* W_nobj = (const float*)d_in[5];
    const float* b_nobj = (const float*)d_in[6];
    const float* W_rel  = (const float*)d_in[7];
    const float* b_rel  = (const float*)d_in[8];
    const float* W_skip = (const float*)d_in[9];
    const float* b_skip = (const float*)d_in[10];
    // d_in[11]/d_in[12] (Wa_w, Wa_b) provably cancel: softmax rows sum to 1,
    // so the attention term is the identity on `aggregated`.
    float* out = (float*)d_out;

    k2a_scan<<<dim3(N / TI, JS), 128>>>(A);     // no deps; longest stream first
    k1_proj<<<N / 16, 128>>>(x, r, W_obj, b_obj, W_nobj, b_nobj,
                             W_rel, b_rel, W_skip, b_skip, out);
    k2b_gather<<<dim3(N / TI, JS), 128>>>();
    k3_reduce<<<(N * D / 4) / 256, 256>>>(out);
}

// round 7
// speedup vs baseline: 1.7160x; 1.0239x over previous
#include <cuda_runtime.h>
#include <cstdint>
#include <cstddef>

#define N 8192
#define D 64

// ---- k2 config ----
#define JS 16                  // j-splits for gather/partials
#define JRANGE (N / JS)        // 512
#define CJ 128                 // j's per chunk
#define NCHUNKS_TOTAL (N / CJ) // 64 global chunks
#define NCHUNK (JRANGE / CJ)   // 4 chunks per gather CTA
#define TIB 128                // gather: A-columns per CTA

// scratch (static device arrays: allocation-free per harness rules)
__device__ float g_y[N * D];                      // y = x@W_nobj + b_nobj (2 MB)
__device__ float g_part[JS][N * D];               // j-split partials (33.6 MB)
__device__ uint4 g_mask[NCHUNKS_TOTAL * N];       // bitmask per (chunk, column) (8.4 MB)

// ---------------------------------------------------------------------------
// Kernel 1: out = x@(W_obj+W_skip) + r@W_rel + biases ;  g_y = x@W_nobj+b_nobj
// ---------------------------------------------------------------------------
__global__ __launch_bounds__(128) void k1_proj(
    const float* __restrict__ x, const float* __restrict__ r,
    const float* __restrict__ W_obj, const float* __restrict__ b_obj,
    const float* __restrict__ W_nobj, const float* __restrict__ b_nobj,
    const float* __restrict__ W_rel, const float* __restrict__ b_rel,
    const float* __restrict__ W_skip, const float* __restrict__ b_skip,
    float* __restrict__ out)
{
    __shared__ float Wc[D * D];
    __shared__ float Wn[D * D];
    __shared__ float Wr[D * D];

    const int t = threadIdx.x;
    for (int e = t; e < D * D; e += 128) {
        Wc[e] = W_obj[e] + W_skip[e];
        Wn[e] = W_nobj[e];
        Wr[e] = W_rel[e];
    }
    __syncthreads();

    const int row = blockIdx.x * 16 + (t >> 3);
    const int d0 = (t & 7) * 8;

    float ab[8], ay[8];
#pragma unroll
    for (int q = 0; q < 8; q++) { ab[q] = 0.f; ay[q] = 0.f; }

    const float4* xp = (const float4*)(x + row * D);
    const float4* rp = (const float4*)(r + row * D);

#pragma unroll 4
    for (int k4 = 0; k4 < D / 4; k4++) {
        const float4 xq = xp[k4];
        const float4 rq = rp[k4];
        const float xv[4] = {xq.x, xq.y, xq.z, xq.w};
        const float rv[4] = {rq.x, rq.y, rq.z, rq.w};
#pragma unroll
        for (int u = 0; u < 4; u++) {
            const int k = k4 * 4 + u;
            const float4 c0 = *(const float4*)&Wc[k * D + d0];
            const float4 c1 = *(const float4*)&Wc[k * D + d0 + 4];
            const float4 n0 = *(const float4*)&Wn[k * D + d0];
            const float4 n1 = *(const float4*)&Wn[k * D + d0 + 4];
            const float4 q0 = *(const float4*)&Wr[k * D + d0];
            const float4 q1 = *(const float4*)&Wr[k * D + d0 + 4];
            const float cc[8] = {c0.x,c0.y,c0.z,c0.w,c1.x,c1.y,c1.z,c1.w};
            const float nn[8] = {n0.x,n0.y,n0.z,n0.w,n1.x,n1.y,n1.z,n1.w};
            const float qq[8] = {q0.x,q0.y,q0.z,q0.w,q1.x,q1.y,q1.z,q1.w};
#pragma unroll
            for (int q = 0; q < 8; q++) {
                ab[q] += xv[u] * cc[q] + rv[u] * qq[q];
                ay[q] += xv[u] * nn[q];
            }
        }
    }

    float4 o0, o1, y0, y1;
    o0.x = ab[0]+b_obj[d0+0]+b_skip[d0+0]+b_rel[d0+0];
    o0.y = ab[1]+b_obj[d0+1]+b_skip[d0+1]+b_rel[d0+1];
    o0.z = ab[2]+b_obj[d0+2]+b_skip[d0+2]+b_rel[d0+2];
    o0.w = ab[3]+b_obj[d0+3]+b_skip[d0+3]+b_rel[d0+3];
    o1.x = ab[4]+b_obj[d0+4]+b_skip[d0+4]+b_rel[d0+4];
    o1.y = ab[5]+b_obj[d0+5]+b_skip[d0+5]+b_rel[d0+5];
    o1.z = ab[6]+b_obj[d0+6]+b_skip[d0+6]+b_rel[d0+6];
    o1.w = ab[7]+b_obj[d0+7]+b_skip[d0+7]+b_rel[d0+7];
    y0.x = ay[0]+b_nobj[d0+0]; y0.y = ay[1]+b_nobj[d0+1];
    y0.z = ay[2]+b_nobj[d0+2]; y0.w = ay[3]+b_nobj[d0+3];
    y1.x = ay[4]+b_nobj[d0+4]; y1.y = ay[5]+b_nobj[d0+5];
    y1.z = ay[6]+b_nobj[d0+6]; y1.w = ay[7]+b_nobj[d0+7];
    float4* op = (float4*)(out + row * D + d0);
    float4* yp = (float4*)(g_y + row * D + d0);
    op[0] = o0; op[1] = o1;
    yp[0] = y0; yp[1] = y1;
}

// ---------------------------------------------------------------------------
// Kernel 2a: A stream -> bitmasks, LDG.128-based, NO spills.
// CTA = (512 columns via float4, one 128-j chunk). Thread owns 4 columns.
// Double-buffered 8xfloat4 batches; 64 buffer regs under a 128-reg budget.
// ---------------------------------------------------------------------------
__global__ __launch_bounds__(128, 4) void k2a_scan(const float* __restrict__ A)
{
    const int t = threadIdx.x;
    const int chunk = blockIdx.y;                 // global chunk 0..63
    const int i0 = blockIdx.x * 512 + 4 * t;      // first of 4 owned columns
    const int rowstride = N / 4;                  // float4 elems per A row

    const float4* Ap = (const float4*)A + (size_t)chunk * CJ * rowstride + (i0 >> 2);

    float4 B0[8], B1[8];
    unsigned m[4][4];
#pragma unroll
    for (int q = 0; q < 4; q++)
#pragma unroll
        for (int wd = 0; wd < 4; wd++) m[q][wd] = 0u;

#pragma unroll
    for (int u = 0; u < 8; u++)
        B0[u] = __ldcs(Ap + (size_t)u * rowstride);

#pragma unroll
    for (int b = 0; b < 16; b++) {                // 16 batches x 8 j = 128 j
        // issue next batch into the other buffer (compile-time selected)
        if (b < 15) {
            if (b & 1) {
#pragma unroll
                for (int u = 0; u < 8; u++)
                    B0[u] = __ldcs(Ap + (size_t)((b + 1) * 8 + u) * rowstride);
            } else {
#pragma unroll
                for (int u = 0; u < 8; u++)
                    B1[u] = __ldcs(Ap + (size_t)((b + 1) * 8 + u) * rowstride);
            }
        }
#pragma unroll
        for (int u = 0; u < 8; u++) {
            const float4 v = (b & 1) ? B1[u] : B0[u];
            const int jl = b * 8 + u;             // compile-time
            const int wd = jl >> 5;
            const unsigned bit = 1u << (jl & 31);
            if (v.x != 0.0f) m[0][wd] |= bit;
            if (v.y != 0.0f) m[1][wd] |= bit;
            if (v.z != 0.0f) m[2][wd] |= bit;
            if (v.w != 0.0f) m[3][wd] |= bit;
        }
    }

    uint4* mp = g_mask + (size_t)chunk * N + i0;
#pragma unroll
    for (int q = 0; q < 4; q++)
        mp[q] = make_uint4(m[q][0], m[q][1], m[q][2], m[q][3]);
}

// ---------------------------------------------------------------------------
// Kernel 2b: gather. CTA = 128 rows (i) x one j-split. Per chunk: stage y
// (32 KB), warp walks its 32 rows via broadcast uint4 mask + ffs,
// lane owns a d-pair; conflict-free LDS.64; register accumulators.
// ---------------------------------------------------------------------------
__global__ __launch_bounds__(128, 4) void k2b_gather()
{
    __shared__ float y_s[CJ * D];   // 32 KB

    const int t = threadIdx.x;
    const int w = t >> 5, lane = t & 31;
    const int i_base = blockIdx.x * TIB;
    const int jy = blockIdx.y;
    const size_t j_base = (size_t)jy * JRANGE;

    float accx[32], accy[32];
#pragma unroll
    for (int il = 0; il < 32; il++) { accx[il] = 0.f; accy[il] = 0.f; }

    for (int c = 0; c < NCHUNK; c++) {
        {
            const float4* ys = (const float4*)(g_y + (j_base + c * CJ) * D);
            float4* yd = (float4*)y_s;
#pragma unroll
            for (int e = 0; e < (CJ * D / 4) / 128; e++)   // 16
                yd[e * 128 + t] = ys[e * 128 + t];
        }
        __syncthreads();

        const int chunk = jy * NCHUNK + c;                 // global chunk
        const uint4* mrow = g_mask + (size_t)chunk * N + i_base;
        const float2* y2 = (const float2*)y_s;

#pragma unroll 4
        for (int il = 0; il < 32; il++) {
            const int iloc = (w << 5) | il;
            const uint4 mv = __ldg(mrow + iloc);           // uniform per warp
            float ax = 0.f, ay = 0.f;
            const unsigned mwords[4] = {mv.x, mv.y, mv.z, mv.w};
#pragma unroll
            for (int k4 = 0; k4 < 4; k4++) {
                unsigned mm = mwords[k4];
                while (mm) {
                    const int b = __ffs(mm) - 1;
                    mm &= mm - 1;
                    const float2 v = y2[(k4 * 32 + b) * 32 + lane];
                    ax += v.x; ay += v.y;
                }
            }
            accx[il] += ax;
            accy[il] += ay;
        }
        __syncthreads();   // y_s free for restage
    }

#pragma unroll
    for (int il = 0; il < 32; il++) {
        const int i = i_base + (w << 5) + il;
        ((float2*)&g_part[jy][(size_t)i * D])[lane] = make_float2(accx[il], accy[il]);
    }
}

// ---------------------------------------------------------------------------
// Kernel 3: out += sum over the JS partials (fixed order -> deterministic)
// ---------------------------------------------------------------------------
__global__ __launch_bounds__(256) void k3_reduce(float* __restrict__ out)
{
    const int g = blockIdx.x * blockDim.x + threadIdx.x;
    float4 v = ((const float4*)out)[g];
#pragma unroll
    for (int s = 0; s < JS; s++) {
        const float4 p = ((const float4*)(&g_part[s][0]))[g];
        v.x += p.x; v.y += p.y; v.z += p.z; v.w += p.w;
    }
    ((float4*)out)[g] = v;
}

// ---------------------------------------------------------------------------
extern "C" void kernel_launch(void* const* d_in, const int* in_sizes, int n_in,
                              void* d_out, int out_size)
{
    const float* x      = (const float*)d_in[0];
    const float* r      = (const float*)d_in[1];
    const float* A      = (const float*)d_in[2];
    const float* W_obj  = (const float*)d_in[3];
    const float* b_obj  = (const float*)d_in[4];
    const float* W_nobj = (const float*)d_in[5];
    const float* b_nobj = (const float*)d_in[6];
    const float* W_rel  = (const float*)d_in[7];
    const float* b_rel  = (const float*)d_in[8];
    const float* W_skip = (const float*)d_in[9];
    const float* b_skip = (const float*)d_in[10];
    // d_in[11]/d_in[12] (Wa_w, Wa_b) provably cancel: softmax rows sum to 1,
    // so the attention term is the identity on `aggregated`.
    float* out = (float*)d_out;

    k2a_scan<<<dim3(N / 512, NCHUNKS_TOTAL), 128>>>(A);   // longest stream first
    k1_proj<<<N / 16, 128>>>(x, r, W_obj, b_obj, W_nobj, b_nobj,
                             W_rel, b_rel, W_skip, b_skip, out);
    k2b_gather<<<dim3(N / TIB, JS), 128>>>();
    k3_reduce<<<(N * D / 4) / 256, 256>>>(out);
}

// round 8
// speedup vs baseline: 1.7676x; 1.0300x over previous
#include <cuda_runtime.h>
#include <cstdint>
#include <cstddef>

#define N 8192
#define D 64

// ---- k2 config ----
#define JS 8                   // j-splits for gather/partials
#define JRANGE (N / JS)        // 1024
#define CJ 128                 // j's per chunk
#define NCHUNKS_TOTAL (N / CJ) // 64 global chunks
#define NCHUNK (JRANGE / CJ)   // 8 chunks per gather CTA
#define TIB 128                // gather: A-columns per CTA

// scratch (static device arrays: allocation-free per harness rules)
__device__ float g_y[N * D];                      // y = x@W_nobj + b_nobj (2 MB)
__device__ float g_part[JS][N * D];               // j-split partials (16.8 MB)
__device__ uint4 g_mask[NCHUNKS_TOTAL * N];       // bitmask per (chunk, column) (8.4 MB)

// ---------------------------------------------------------------------------
// Kernel 1: out = x@(W_obj+W_skip) + r@W_rel + biases ;  g_y = x@W_nobj+b_nobj
// ---------------------------------------------------------------------------
__global__ __launch_bounds__(128) void k1_proj(
    const float* __restrict__ x, const float* __restrict__ r,
    const float* __restrict__ W_obj, const float* __restrict__ b_obj,
    const float* __restrict__ W_nobj, const float* __restrict__ b_nobj,
    const float* __restrict__ W_rel, const float* __restrict__ b_rel,
    const float* __restrict__ W_skip, const float* __restrict__ b_skip,
    float* __restrict__ out)
{
    __shared__ float Wc[D * D];
    __shared__ float Wn[D * D];
    __shared__ float Wr[D * D];

    const int t = threadIdx.x;
    for (int e = t; e < D * D; e += 128) {
        Wc[e] = W_obj[e] + W_skip[e];
        Wn[e] = W_nobj[e];
        Wr[e] = W_rel[e];
    }
    __syncthreads();

    const int row = blockIdx.x * 16 + (t >> 3);
    const int d0 = (t & 7) * 8;

    float ab[8], ay[8];
#pragma unroll
    for (int q = 0; q < 8; q++) { ab[q] = 0.f; ay[q] = 0.f; }

    const float4* xp = (const float4*)(x + row * D);
    const float4* rp = (const float4*)(r + row * D);

#pragma unroll 4
    for (int k4 = 0; k4 < D / 4; k4++) {
        const float4 xq = xp[k4];
        const float4 rq = rp[k4];
        const float xv[4] = {xq.x, xq.y, xq.z, xq.w};
        const float rv[4] = {rq.x, rq.y, rq.z, rq.w};
#pragma unroll
        for (int u = 0; u < 4; u++) {
            const int k = k4 * 4 + u;
            const float4 c0 = *(const float4*)&Wc[k * D + d0];
            const float4 c1 = *(const float4*)&Wc[k * D + d0 + 4];
            const float4 n0 = *(const float4*)&Wn[k * D + d0];
            const float4 n1 = *(const float4*)&Wn[k * D + d0 + 4];
            const float4 q0 = *(const float4*)&Wr[k * D + d0];
            const float4 q1 = *(const float4*)&Wr[k * D + d0 + 4];
            const float cc[8] = {c0.x,c0.y,c0.z,c0.w,c1.x,c1.y,c1.z,c1.w};
            const float nn[8] = {n0.x,n0.y,n0.z,n0.w,n1.x,n1.y,n1.z,n1.w};
            const float qq[8] = {q0.x,q0.y,q0.z,q0.w,q1.x,q1.y,q1.z,q1.w};
#pragma unroll
            for (int q = 0; q < 8; q++) {
                ab[q] += xv[u] * cc[q] + rv[u] * qq[q];
                ay[q] += xv[u] * nn[q];
            }
        }
    }

    float4 o0, o1, y0, y1;
    o0.x = ab[0]+b_obj[d0+0]+b_skip[d0+0]+b_rel[d0+0];
    o0.y = ab[1]+b_obj[d0+1]+b_skip[d0+1]+b_rel[d0+1];
    o0.z = ab[2]+b_obj[d0+2]+b_skip[d0+2]+b_rel[d0+2];
    o0.w = ab[3]+b_obj[d0+3]+b_skip[d0+3]+b_rel[d0+3];
    o1.x = ab[4]+b_obj[d0+4]+b_skip[d0+4]+b_rel[d0+4];
    o1.y = ab[5]+b_obj[d0+5]+b_skip[d0+5]+b_rel[d0+5];
    o1.z = ab[6]+b_obj[d0+6]+b_skip[d0+6]+b_rel[d0+6];
    o1.w = ab[7]+b_obj[d0+7]+b_skip[d0+7]+b_rel[d0+7];
    y0.x = ay[0]+b_nobj[d0+0]; y0.y = ay[1]+b_nobj[d0+1];
    y0.z = ay[2]+b_nobj[d0+2]; y0.w = ay[3]+b_nobj[d0+3];
    y1.x = ay[4]+b_nobj[d0+4]; y1.y = ay[5]+b_nobj[d0+5];
    y1.z = ay[6]+b_nobj[d0+6]; y1.w = ay[7]+b_nobj[d0+7];
    float4* op = (float4*)(out + row * D + d0);
    float4* yp = (float4*)(g_y + row * D + d0);
    op[0] = o0; op[1] = o1;
    yp[0] = y0; yp[1] = y1;
}

// ---------------------------------------------------------------------------
// Kernel 2a: A stream -> bitmasks. MINIMAL per-thread state for max residency.
// Thread = one column x one 128-j chunk: 4x(32 unrolled LDG.32 -> mask word),
// one uint4 store. ~50 regs -> 40+ warps/SM; 32 outstanding lines per warp.
// ---------------------------------------------------------------------------
__global__ __launch_bounds__(256) void k2a_scan(const float* __restrict__ A)
{
    const int i = blockIdx.x * 256 + threadIdx.x;   // column (coalesced per warp)
    const int chunk = blockIdx.y;                   // 0..63
    const float* Ap = A + (size_t)chunk * CJ * N + i;

    unsigned mw[4];
#pragma unroll
    for (int w4 = 0; w4 < 4; w4++) {
        float av[32];
#pragma unroll
        for (int u = 0; u < 32; u++)                // 32 independent LDG.32
            av[u] = __ldcs(Ap + (size_t)(w4 * 32 + u) * N);
        unsigned m = 0;
#pragma unroll
        for (int u = 0; u < 32; u++)
            if (av[u] != 0.0f) m |= (1u << u);
        mw[w4] = m;
    }
    g_mask[(size_t)chunk * N + i] = make_uint4(mw[0], mw[1], mw[2], mw[3]);
}

// ---------------------------------------------------------------------------
// Kernel 2b: gather. CTA = 128 rows (i) x one j-split. Per chunk: stage y
// (32 KB), warp walks its 32 rows via broadcast uint4 mask + ffs,
// lane owns a d-pair; conflict-free LDS.64; register accumulators.
// ---------------------------------------------------------------------------
__global__ __launch_bounds__(128, 4) void k2b_gather()
{
    __shared__ float y_s[CJ * D];   // 32 KB

    const int t = threadIdx.x;
    const int w = t >> 5, lane = t & 31;
    const int i_base = blockIdx.x * TIB;
    const int jy = blockIdx.y;
    const size_t j_base = (size_t)jy * JRANGE;

    float accx[32], accy[32];
#pragma unroll
    for (int il = 0; il < 32; il++) { accx[il] = 0.f; accy[il] = 0.f; }

    for (int c = 0; c < NCHUNK; c++) {
        {
            const float4* ys = (const float4*)(g_y + (j_base + c * CJ) * D);
            float4* yd = (float4*)y_s;
#pragma unroll
            for (int e = 0; e < (CJ * D / 4) / 128; e++)   // 16
                yd[e * 128 + t] = ys[e * 128 + t];
        }
        __syncthreads();

        const int chunk = jy * NCHUNK + c;                 // global chunk
        const uint4* mrow = g_mask + (size_t)chunk * N + i_base;
        const float2* y2 = (const float2*)y_s;

#pragma unroll 4
        for (int il = 0; il < 32; il++) {
            const int iloc = (w << 5) | il;
            const uint4 mv = __ldg(mrow + iloc);           // uniform per warp
            float ax = 0.f, ay = 0.f;
            const unsigned mwords[4] = {mv.x, mv.y, mv.z, mv.w};
#pragma unroll
            for (int k4 = 0; k4 < 4; k4++) {
                unsigned mm = mwords[k4];
                while (mm) {
                    const int b = __ffs(mm) - 1;
                    mm &= mm - 1;
                    const float2 v = y2[(k4 * 32 + b) * 32 + lane];
                    ax += v.x; ay += v.y;
                }
            }
            accx[il] += ax;
            accy[il] += ay;
        }
        __syncthreads();   // y_s free for restage
    }

#pragma unroll
    for (int il = 0; il < 32; il++) {
        const int i = i_base + (w << 5) + il;
        ((float2*)&g_part[jy][(size_t)i * D])[lane] = make_float2(accx[il], accy[il]);
    }
}

// ---------------------------------------------------------------------------
// Kernel 3: out += sum over the JS partials (fixed order -> deterministic)
// ---------------------------------------------------------------------------
__global__ __launch_bounds__(256) void k3_reduce(float* __restrict__ out)
{
    const int g = blockIdx.x * blockDim.x + threadIdx.x;
    float4 v = ((const float4*)out)[g];
#pragma unroll
    for (int s = 0; s < JS; s++) {
        const float4 p = ((const float4*)(&g_part[s][0]))[g];
        v.x += p.x; v.y += p.y; v.z += p.z; v.w += p.w;
    }
    ((float4*)out)[g] = v;
}

// ---------------------------------------------------------------------------
extern "C" void kernel_launch(void* const* d_in, const int* in_sizes, int n_in,
                              void* d_out, int out_size)
{
    const float* x      = (const float*)d_in[0];
    const float* r      = (const float*)d_in[1];
    const float* A      = (const float*)d_in[2];
    const float* W_obj  = (const float*)d_in[3];
    const float* b_obj  = (const float*)d_in[4];
    const float* W_nobj = (const float*)d_in[5];
    const float* b_nobj = (const float*)d_in[6];
    const float* W_rel  = (const float*)d_in[7];
    const float* b_rel  = (const float*)d_in[8];
    const float* W_skip = (const float*)d_in[9];
    const float* b_skip = (const float*)d_in[10];
    // d_in[11]/d_in[12] (Wa_w, Wa_b) provably cancel: softmax rows sum to 1,
    // so the attention term is the identity on `aggregated`.
    float* out = (float*)d_out;

    k2a_scan<<<dim3(N / 256, NCHUNKS_TOTAL), 256>>>(A);   // longest stream first
    k1_proj<<<N / 16, 128>>>(x, r, W_obj, b_obj, W_nobj, b_nobj,
                             W_rel, b_rel, W_skip, b_skip, out);
    k2b_gather<<<dim3(N / TIB, JS), 128>>>();
    k3_reduce<<<(N * D / 4) / 256, 256>>>(out);
}